// round 11
// baseline (speedup 1.0000x reference)
#include <cuda_runtime.h>
#include <cuda_bf16.h>
#include <math.h>
#include <stdint.h>

#define NN 131072
#define DD 256
#define KK 1024
#define EPSV 1e-5f
#define DECAYV 0.99f
#define GAP_EPS 5e-4f

// ---- scratch (no allocations allowed) ----
__device__ float g_xnorm[NN];
__device__ float g_enorm[KK];
__device__ int   g_idx[NN];
__device__ int   g_counts[KK];
__device__ int   g_offsets[KK];
__device__ int   g_cursor[KK];
__device__ int   g_bucket[NN];
__device__ float g_ncs[KK];
__device__ float g_ntotal;
__device__ float g_mse;
__device__ float g_ortho;
// embedding bf16 (hi part only)
__device__ __align__(16) __nv_bfloat16 g_eh[KK * DD];

// ======================= PTX helpers (all compute_103-safe) =======================
__device__ __forceinline__ uint32_t smem_to_u32(const void* p) {
    uint32_t a;
    asm("{ .reg .u64 t; cvta.to.shared.u64 t, %1; cvt.u32.u64 %0, t; }" : "=r"(a) : "l"(p));
    return a;
}
#define LDSM_X4(r0, r1, r2, r3, addr) \
    asm volatile("ldmatrix.sync.aligned.m8n8.x4.shared.b16 {%0,%1,%2,%3}, [%4];" \
                 : "=r"(r0), "=r"(r1), "=r"(r2), "=r"(r3) : "r"(addr))
#define MMA16816(c, a0, a1, a2, a3, b0, b1) \
    asm volatile("mma.sync.aligned.m16n8k16.row.col.f32.bf16.bf16.f32 " \
                 "{%0,%1,%2,%3},{%4,%5,%6,%7},{%8,%9},{%0,%1,%2,%3};" \
                 : "+f"((c)[0]), "+f"((c)[1]), "+f"((c)[2]), "+f"((c)[3]) \
                 : "r"(a0), "r"(a1), "r"(a2), "r"(a3), "r"(b0), "r"(b1))
#define CPA16(dst, src) \
    asm volatile("cp.async.cg.shared.global [%0], [%1], 16;" :: "r"(dst), "l"(src))
#define CPA_COMMIT() asm volatile("cp.async.commit_group;" ::: "memory")

// ======================= smem layout =======================
// A_h[128][264 bf16] stride 528B; B ring: 3 bufs of 128 codes x (128 bf16 + pad) stride 272B
#define SA_H   0
#define SB_B   67584
#define SB_STR 272
#define SB_SZ  34816
#define S_PK   172032
#define S_OVFN 188416
#define S_OVFR 188424
#define SMEM_TOTAL 188960

// ======================= small kernels =======================
__global__ void k_init() {
    int t = blockIdx.x * blockDim.x + threadIdx.x;
    if (t < KK) { g_counts[t] = 0; g_cursor[t] = 0; }
    if (t == 0) { g_mse = 0.f; g_ortho = 0.f; }
}

__global__ __launch_bounds__(256) void k_embh(const float* __restrict__ emb) {
    int i = blockIdx.x * 256 + threadIdx.x;  // over KK*DD/4
    float4 v = ((const float4*)emb)[i];
    unsigned short h0 = __bfloat16_as_ushort(__float2bfloat16(v.x));
    unsigned short h1 = __bfloat16_as_ushort(__float2bfloat16(v.y));
    unsigned short h2 = __bfloat16_as_ushort(__float2bfloat16(v.z));
    unsigned short h3 = __bfloat16_as_ushort(__float2bfloat16(v.w));
    uint2 u;
    u.x = (uint32_t)h0 | ((uint32_t)h1 << 16);
    u.y = (uint32_t)h2 | ((uint32_t)h3 << 16);
    ((uint2*)g_eh)[i] = u;
}

__global__ __launch_bounds__(256) void k_norms(const float* __restrict__ flat,
                                               const float* __restrict__ emb) {
    int warp = (blockIdx.x * blockDim.x + threadIdx.x) >> 5;
    int lane = threadIdx.x & 31;
    if (warp >= NN + KK) return;
    const float4* p4 = (warp < NN)
        ? (const float4*)(flat + (size_t)warp * DD)
        : (const float4*)(emb + (size_t)(warp - NN) * DD);
    float s = 0.f;
#pragma unroll
    for (int c = 0; c < 2; c++) {
        float4 v = p4[lane + 32 * c];
        s += v.x * v.x + v.y * v.y + v.z * v.z + v.w * v.w;
    }
#pragma unroll
    for (int o = 16; o; o >>= 1) s += __shfl_xor_sync(0xffffffffu, s, o);
    if (lane == 0) {
        if (warp < NN) g_xnorm[warp] = s;
        else           g_enorm[warp - NN] = s;
    }
}

// exact fp32 rescore of one (row, code) distance — reference-style rounding
__device__ __forceinline__ float exact_dist(const float4* __restrict__ f4,
                                            const float4* __restrict__ e4,
                                            int n, int k, float xn) {
    float s0 = 0.f, s1 = 0.f, s2 = 0.f, s3 = 0.f;
#pragma unroll 8
    for (int c = 0; c < 64; c++) {
        float4 x = f4[(size_t)n * 64 + c];
        float4 e = e4[(size_t)k * 64 + c];
        s0 += x.x * e.x; s1 += x.y * e.y; s2 += x.z * e.z; s3 += x.w * e.w;
    }
    float dot = (s0 + s1) + (s2 + s3);
    return (xn + g_enorm[k]) - 2.0f * dot;
}

// packed (score_bits<<32 | k): positive scores => uint64 order == (score, k) lexicographic
__device__ __forceinline__ unsigned long long pk_make(float v, int k) {
    return ((unsigned long long)(uint32_t)__float_as_int(v) << 32) | (uint32_t)k;
}
__device__ __forceinline__ float pk_val(unsigned long long p) {
    return __int_as_float((int)(p >> 32));
}
__device__ __forceinline__ int pk_idx(unsigned long long p) {
    return (int)(p & 0xffffffffu);
}
#define PK_SENT 0x7f7fffff00000000ull

// insert p into sorted top-4 t0<=t1<=t2<=t3 (assumes p < t3 already checked)
#define TOP4_INS(t0, t1, t2, t3, p) do { \
    unsigned long long _p = (p); \
    if (_p < (t2)) { (t3) = (t2); \
        if (_p < (t1)) { (t2) = (t1); \
            if (_p < (t0)) { (t1) = (t0); (t0) = _p; } else (t1) = _p; \
        } else (t2) = _p; \
    } else (t3) = _p; } while (0)

// ======================= bf16 HMMA argmin (hh-only, reg top-4, exact rescore) ===========
// CTA: 512 threads = 16 warps (wm 0..3 x 32 rows, wn 0..3 x 32 cols); 128 rows x 1024 codes.
// A holds bf16(-2x); approx score d = (1+||e||^2) + acc ~ 1 + ||e||^2 - 2 x.e.
// Per-thread register top-4 per row-slot (no atomics/barriers in epilogue);
// merged top-4 per row; exact fp32 rescore of all cands < min+GAP; full-scan fallback
// whenever any merged 4th-best < min+GAP (superset guarantee).
__global__ __launch_bounds__(512, 1) void k_argmin_mma(const float* __restrict__ flat,
                                                       const float* __restrict__ emb,
                                                       float* __restrict__ out_idx) {
    extern __shared__ __align__(16) char smem[];
    uint32_t sb = smem_to_u32(smem);
    int tid = threadIdx.x;
    int lane = tid & 31, wid = tid >> 5;
    int wm = wid >> 2, wn = wid & 3;
    int rowbase = blockIdx.x * 128;

    unsigned long long* s_pk = (unsigned long long*)(smem + S_PK);
    int* s_novf = (int*)(smem + S_OVFN);
    int* s_ovfr = (int*)(smem + S_OVFR);

    // ---- phase 0: load A fp32, store bf16(-2x) into persistent smem ----
    const float4* f4 = (const float4*)flat;
#pragma unroll
    for (int it = 0; it < 16; it++) {
        int idx = it * 512 + tid;
        int r = idx >> 6, c4 = idx & 63;
        float4 v = f4[((size_t)(rowbase + r)) * 64 + c4];
        unsigned short h0 = __bfloat16_as_ushort(__float2bfloat16(-2.0f * v.x));
        unsigned short h1 = __bfloat16_as_ushort(__float2bfloat16(-2.0f * v.y));
        unsigned short h2 = __bfloat16_as_ushort(__float2bfloat16(-2.0f * v.z));
        unsigned short h3 = __bfloat16_as_ushort(__float2bfloat16(-2.0f * v.w));
        uint2 u;
        u.x = (uint32_t)h0 | ((uint32_t)h1 << 16);
        u.y = (uint32_t)h2 | ((uint32_t)h3 << 16);
        *(uint2*)(smem + SA_H + r * 528 + c4 * 8) = u;
    }
    if (tid == 0) *s_novf = 0;

    float acc[2][4][4];
#pragma unroll
    for (int i = 0; i < 2; i++)
#pragma unroll
        for (int nf = 0; nf < 4; nf++)
#pragma unroll
            for (int c = 0; c < 4; c++) acc[i][nf][c] = 0.f;

    // per-slot top-4 (packed) + float shadow of 4th for the cheap guard compare
    unsigned long long t4[4][4];
    float t3f[4];
#pragma unroll
    for (int s = 0; s < 4; s++) {
        t4[s][0] = t4[s][1] = t4[s][2] = t4[s][3] = PK_SENT;
        t3f[s] = 3.4e38f;
    }

    // lane-derived ldmatrix addressing
    int a_row = lane & 15;
    int a_kof = (lane >> 4) * 8;
    int b_nof = (lane & 7) + ((lane >> 4) & 1) * 8;
    int b_kof = ((lane >> 3) & 1) * 8;
    int pr = tid >> 2, pq = tid & 3;  // prefetch row / 64B quarter

    // prefetch chunk 0; chunk gc: nt = gc>>1 (128 codes), ci = gc&1 (128-dim half)
    {
        const char* gs = (const char*)g_eh + (size_t)pr * 512 + pq * 64;
        uint32_t ds = sb + SB_B + pr * SB_STR + pq * 64;
        CPA16(ds, gs); CPA16(ds + 16, gs + 16); CPA16(ds + 32, gs + 32); CPA16(ds + 48, gs + 48);
        CPA_COMMIT();
    }

    for (int gc = 0; gc < 16; gc++) {
        int nt = gc >> 1, ci = gc & 1;
        if (gc < 15) {
            int nt2 = (gc + 1) >> 1, ci2 = (gc + 1) & 1;
            const char* gs = (const char*)g_eh + ((size_t)(nt2 * 128 + pr)) * 512 + ci2 * 256 + pq * 64;
            uint32_t ds = sb + SB_B + ((gc + 1) % 3) * SB_SZ + pr * SB_STR + pq * 64;
            CPA16(ds, gs); CPA16(ds + 16, gs + 16); CPA16(ds + 32, gs + 32); CPA16(ds + 48, gs + 48);
            CPA_COMMIT();
            asm volatile("cp.async.wait_group 1;" ::: "memory");
        } else {
            asm volatile("cp.async.wait_group 0;" ::: "memory");
        }
        __syncthreads();  // chunk gc visible; 3-buf ring covers WAR

        int kb = ci * 128;
        uint32_t bbase = sb + SB_B + (gc % 3) * SB_SZ;
#pragma unroll
        for (int kk = 0; kk < 8; kk++) {
            uint32_t b[2][4];
#pragma unroll
            for (int p = 0; p < 2; p++) {
                uint32_t bd = bbase + (uint32_t)(wn * 32 + p * 16 + b_nof) * SB_STR
                            + (uint32_t)(kk * 16 + b_kof) * 2u;
                LDSM_X4(b[p][0], b[p][1], b[p][2], b[p][3], bd);
            }
            uint32_t a[2][4];
#pragma unroll
            for (int i = 0; i < 2; i++) {
                uint32_t ad = sb + SA_H + (uint32_t)(wm * 32 + i * 16 + a_row) * 528u
                            + (uint32_t)(kb + kk * 16 + a_kof) * 2u;
                LDSM_X4(a[i][0], a[i][1], a[i][2], a[i][3], ad);
            }
#pragma unroll
            for (int i = 0; i < 2; i++) {
                MMA16816(acc[i][0], a[i][0], a[i][1], a[i][2], a[i][3], b[0][0], b[0][1]);
                MMA16816(acc[i][1], a[i][0], a[i][1], a[i][2], a[i][3], b[0][2], b[0][3]);
                MMA16816(acc[i][2], a[i][0], a[i][1], a[i][2], a[i][3], b[1][0], b[1][1]);
                MMA16816(acc[i][3], a[i][0], a[i][1], a[i][2], a[i][3], b[1][2], b[1][3]);
            }
        }

        if (ci == 1) {
            // ---- epilogue: scores -> per-slot register top-4 (no syncs, no atomics) ----
#pragma unroll
            for (int nf = 0; nf < 4; nf++) {
                int cb = nt * 128 + wn * 32 + nf * 8 + (lane & 3) * 2;
                float en0 = 1.0f + __ldg(&g_enorm[cb]);
                float en1 = 1.0f + __ldg(&g_enorm[cb + 1]);
#pragma unroll
                for (int i = 0; i < 2; i++) {
#pragma unroll
                    for (int c = 0; c < 4; c++) {
                        int s = i * 2 + (c >> 1);
                        float d = acc[i][nf][c] + ((c & 1) ? en1 : en0);
                        if (d < t3f[s]) {
                            unsigned long long p = pk_make(d, cb + (c & 1));
                            if (p < t4[s][3]) {
                                TOP4_INS(t4[s][0], t4[s][1], t4[s][2], t4[s][3], p);
                                t3f[s] = pk_val(t4[s][3]);
                            }
                        }
                        acc[i][nf][c] = 0.f;
                    }
                }
            }
        }
    }

    // ---- cross-lane merge (4 lanes share each row-slot) ----
#pragma unroll
    for (int off = 1; off <= 2; off <<= 1)
#pragma unroll
        for (int s = 0; s < 4; s++) {
#pragma unroll
            for (int r = 0; r < 4; r++) {
                unsigned long long o = __shfl_xor_sync(0xffffffffu, t4[s][r], off);
                if (o < t4[s][3]) TOP4_INS(t4[s][0], t4[s][1], t4[s][2], t4[s][3], o);
            }
        }
    if ((lane & 3) == 0) {
#pragma unroll
        for (int s = 0; s < 4; s++) {
            int row = wm * 32 + (s >> 1) * 16 + (s & 1) * 8 + (lane >> 2);
#pragma unroll
            for (int r = 0; r < 4; r++) s_pk[row * 16 + wn * 4 + r] = t4[s][r];
        }
    }
    __syncthreads();

    // ---- per-row selection: exact rescore of superset, fallback full scan ----
    const float4* e4 = (const float4*)emb;
    if (tid < 128) {
        int n = rowbase + tid;
        unsigned long long m = s_pk[tid * 16];
#pragma unroll
        for (int w = 1; w < 4; w++) {
            unsigned long long v = s_pk[tid * 16 + w * 4];
            if (v < m) m = v;
        }
        float thr = pk_val(m) + GAP_EPS;
        bool susp = false;
#pragma unroll
        for (int w = 0; w < 4; w++)
            susp |= (pk_val(s_pk[tid * 16 + w * 4 + 3]) < thr);
        if (susp) {
            int p = atomicAdd(s_novf, 1);
            s_ovfr[p] = tid;
        } else {
            float xn = g_xnorm[n];
            float bv = 3.4e38f;
            int bk = 1 << 30;
            for (int j = 0; j < 16; j++) {
                unsigned long long p = s_pk[tid * 16 + j];
                if (pk_val(p) < thr) {
                    int k = pk_idx(p);
                    float d = exact_dist(f4, e4, n, k, xn);
                    if (d < bv || (d == bv && k < bk)) { bv = d; bk = k; }
                }
            }
            g_idx[n] = bk;
            atomicAdd(&g_counts[bk], 1);
            if (out_idx) out_idx[n] = (float)bk;
        }
    }
    __syncthreads();
    // fallback: warp-cooperative exact full scan (statistically ~never taken)
    int nov = *s_novf;
    for (int o = wid; o < nov; o += 16) {
        int rl = s_ovfr[o];
        int n = rowbase + rl;
        float xn = g_xnorm[n];
        float bv = 3.4e38f;
        int bk = 1 << 30;
        for (int k = lane; k < KK; k += 32) {
            float d = exact_dist(f4, e4, n, k, xn);
            if (d < bv || (d == bv && k < bk)) { bv = d; bk = k; }
        }
#pragma unroll
        for (int off = 16; off; off >>= 1) {
            float ov = __shfl_xor_sync(0xffffffffu, bv, off);
            int ok = __shfl_xor_sync(0xffffffffu, bk, off);
            if (ov < bv || (ov == bv && ok < bk)) { bv = ov; bk = ok; }
        }
        if (lane == 0) {
            g_idx[n] = bk;
            atomicAdd(&g_counts[bk], 1);
            if (out_idx) out_idx[n] = (float)bk;
        }
    }
}

// ======================= EMA / losses (as R10) =======================
__global__ void k_scan(const float* __restrict__ ema_cs, float* __restrict__ out_ncs) {
    __shared__ int   sc[KK];
    __shared__ float red[KK];
    int t = threadIdx.x;
    int c = g_counts[t];
    float ncs = DECAYV * ema_cs[t] + (1.0f - DECAYV) * (float)c;
    g_ncs[t] = ncs;
    if (out_ncs) out_ncs[t] = ncs;
    red[t] = ncs;
    __syncthreads();
#pragma unroll
    for (int o = 512; o; o >>= 1) {
        if (t < o) red[t] += red[t + o];
        __syncthreads();
    }
    if (t == 0) g_ntotal = red[0] + EPSV;
    sc[t] = c;
    __syncthreads();
    for (int o = 1; o < KK; o <<= 1) {
        int u = (t >= o) ? sc[t - o] : 0;
        __syncthreads();
        sc[t] += u;
        __syncthreads();
    }
    g_offsets[t] = sc[t] - c;
}

__global__ __launch_bounds__(256) void k_scatter() {
    int n = blockIdx.x * 256 + threadIdx.x;
    int k = g_idx[n];
    int pos = atomicAdd(&g_cursor[k], 1);
    g_bucket[g_offsets[k] + pos] = n;
}

__global__ __launch_bounds__(256) void k_codesum(const float* __restrict__ flat,
                                                 const float* __restrict__ ema_avg,
                                                 float* __restrict__ out_ne,
                                                 float* __restrict__ out_nea) {
    __shared__ int sn[256];
    int k = blockIdx.x;
    int d = threadIdx.x;
    int start = g_offsets[k];
    int cnt = g_counts[k];
    float s = 0.f;
    for (int base = 0; base < cnt; base += 256) {
        int m = min(256, cnt - base);
        __syncthreads();
        if (d < m) sn[d] = g_bucket[start + base + d];
        __syncthreads();
        int t = 0;
        for (; t + 4 <= m; t += 4) {
            float v0 = flat[(size_t)sn[t + 0] * DD + d];
            float v1 = flat[(size_t)sn[t + 1] * DD + d];
            float v2 = flat[(size_t)sn[t + 2] * DD + d];
            float v3 = flat[(size_t)sn[t + 3] * DD + d];
            s += ((v0 + v1) + (v2 + v3));
        }
        for (; t < m; t++) s += flat[(size_t)sn[t] * DD + d];
    }
    float navg = DECAYV * ema_avg[(size_t)k * DD + d] + (1.0f - DECAYV) * s;
    if (out_nea) out_nea[(size_t)k * DD + d] = navg;
    float cs = (g_ncs[k] + EPSV) / g_ntotal;
    if (out_ne) out_ne[(size_t)k * DD + d] = navg / cs;
}

__global__ __launch_bounds__(256) void k_quant(const float* __restrict__ flat,
                                               const float* __restrict__ emb,
                                               float* __restrict__ out_q) {
    int tid = threadIdx.x;
    int c = tid & 63;
    int rs = tid >> 6;
    int base = blockIdx.x * 64;
    const float4* f4 = (const float4*)flat;
    const float4* e4 = (const float4*)emb;
    float4* o4 = (float4*)out_q;
    float acc = 0.f;
#pragma unroll 4
    for (int it = 0; it < 16; it++) {
        int n = base + it * 4 + rs;
        int k = g_idx[n];
        float4 x = f4[(size_t)n * 64 + c];
        float4 e = e4[(size_t)k * 64 + c];
        float dx = e.x - x.x, dy = e.y - x.y, dz = e.z - x.z, dw = e.w - x.w;
        acc += dx * dx + dy * dy + dz * dz + dw * dw;
        if (out_q) {
            float4 st;
            st.x = x.x + dx; st.y = x.y + dy; st.z = x.z + dz; st.w = x.w + dw;
            o4[(size_t)n * 64 + c] = st;
        }
    }
    __shared__ float red[256];
    red[tid] = acc;
    __syncthreads();
#pragma unroll
    for (int o = 128; o; o >>= 1) {
        if (tid < o) red[tid] += red[tid + o];
        __syncthreads();
    }
    if (tid == 0) atomicAdd(&g_mse, red[0]);
}

__global__ __launch_bounds__(256) void k_ortho(const float* __restrict__ emb) {
    __shared__ float Ei[32][65];
    __shared__ float Ej[32][65];
    int bi = blockIdx.x >> 5;
    int bj = blockIdx.x & 31;
    int tid = threadIdx.x;
    int tx = tid & 15, ty = tid >> 4;
    const float4* e4 = (const float4*)emb;
    float acc[2][2] = {{0.f, 0.f}, {0.f, 0.f}};
    for (int dc = 0; dc < 4; dc++) {
#pragma unroll
        for (int s = 0; s < 2; s++) {
            int i = s * 256 + tid;
            int r = i >> 4, c = i & 15;
            float4 va = e4[(size_t)(bi * 32 + r) * 64 + dc * 16 + c];
            Ei[r][c * 4 + 0] = va.x; Ei[r][c * 4 + 1] = va.y;
            Ei[r][c * 4 + 2] = va.z; Ei[r][c * 4 + 3] = va.w;
            float4 vb = e4[(size_t)(bj * 32 + r) * 64 + dc * 16 + c];
            Ej[r][c * 4 + 0] = vb.x; Ej[r][c * 4 + 1] = vb.y;
            Ej[r][c * 4 + 2] = vb.z; Ej[r][c * 4 + 3] = vb.w;
        }
        __syncthreads();
#pragma unroll 8
        for (int d = 0; d < 64; d++) {
            float a0 = Ei[ty * 2 + 0][d], a1 = Ei[ty * 2 + 1][d];
            float b0 = Ej[tx * 2 + 0][d], b1 = Ej[tx * 2 + 1][d];
            acc[0][0] += a0 * b0; acc[0][1] += a0 * b1;
            acc[1][0] += a1 * b0; acc[1][1] += a1 * b1;
        }
        __syncthreads();
    }
    float s = 0.f;
#pragma unroll
    for (int ii = 0; ii < 2; ii++)
#pragma unroll
        for (int jj = 0; jj < 2; jj++) {
            int gi = bi * 32 + ty * 2 + ii;
            int gj = bj * 32 + tx * 2 + jj;
            if (gi != gj) s += acc[ii][jj] * acc[ii][jj];
        }
    __shared__ float red[256];
    red[tid] = s;
    __syncthreads();
#pragma unroll
    for (int o = 128; o; o >>= 1) {
        if (tid < o) red[tid] += red[tid + o];
        __syncthreads();
    }
    if (tid == 0) atomicAdd(&g_ortho, red[0]);
}

__global__ void k_loss(float* __restrict__ out_loss) {
    float mse_mean = g_mse / 33554432.0f;
    float loss = mse_mean + 0.25f * mse_mean + 0.09f * sqrtf(g_ortho);
    if (out_loss) *out_loss = loss;
}

// ---------------------------------------------------------------------------
extern "C" void kernel_launch(void* const* d_in, const int* in_sizes, int n_in,
                              void* d_out, int out_size) {
    const float* flat    = (const float*)d_in[0];
    const float* emb     = (const float*)d_in[1];
    const float* ema_cs  = (const float*)d_in[2];
    const float* ema_avg = (const float*)d_in[3];
    float* out = (float*)d_out;

    const int FULL = 34210817;
    bool isfull = (out_size >= FULL);
    float* out_q    = out;
    float* out_loss = isfull ? out + 33554432 : nullptr;
    float* out_idx  = isfull ? out + 33554433 : nullptr;
    float* out_ne   = isfull ? out + 33685505 : nullptr;
    float* out_ncs  = isfull ? out + 33947649 : nullptr;
    float* out_nea  = isfull ? out + 33948673 : nullptr;

    cudaFuncSetAttribute(k_argmin_mma, cudaFuncAttributeMaxDynamicSharedMemorySize, SMEM_TOTAL);

    k_init<<<4, 256>>>();
    k_embh<<<KK * DD / 4 / 256, 256>>>(emb);
    k_norms<<<(NN + KK) / 8, 256>>>(flat, emb);
    k_argmin_mma<<<NN / 128, 512, SMEM_TOTAL>>>(flat, emb, out_idx);
    k_scan<<<1, 1024>>>(ema_cs, out_ncs);
    k_scatter<<<NN / 256, 256>>>();
    k_codesum<<<KK, 256>>>(flat, ema_avg, out_ne, out_nea);
    k_quant<<<NN / 64, 256>>>(flat, emb, out_q);
    k_ortho<<<1024, 256>>>(emb);
    k_loss<<<1, 1>>>(out_loss);
}

// round 13
// speedup vs baseline: 2.5140x; 2.5140x over previous
#include <cuda_runtime.h>
#include <cuda_bf16.h>
#include <math.h>
#include <stdint.h>

#define NN 131072
#define DD 256
#define KK 1024
#define EPSV 1e-5f
#define DECAYV 0.99f
#define GAP_EPS 5e-4f
#define CAP 24

// ---- scratch (no allocations allowed) ----
__device__ float g_xnorm[NN];
__device__ float g_enorm[KK];
__device__ int   g_idx[NN];
__device__ int   g_counts[KK];
__device__ int   g_offsets[KK];
__device__ int   g_cursor[KK];
__device__ int   g_bucket[NN];
__device__ float g_ncs[KK];
__device__ float g_ntotal;
__device__ float g_mse;
__device__ float g_ortho;
// embedding bf16 (hi part only)
__device__ __align__(16) __nv_bfloat16 g_eh[KK * DD];

// ======================= PTX helpers (all compute_103-safe) =======================
__device__ __forceinline__ uint32_t smem_to_u32(const void* p) {
    uint32_t a;
    asm("{ .reg .u64 t; cvta.to.shared.u64 t, %1; cvt.u32.u64 %0, t; }" : "=r"(a) : "l"(p));
    return a;
}
#define LDSM_X4(r0, r1, r2, r3, addr) \
    asm volatile("ldmatrix.sync.aligned.m8n8.x4.shared.b16 {%0,%1,%2,%3}, [%4];" \
                 : "=r"(r0), "=r"(r1), "=r"(r2), "=r"(r3) : "r"(addr))
#define MMA16816(c, a0, a1, a2, a3, b0, b1) \
    asm volatile("mma.sync.aligned.m16n8k16.row.col.f32.bf16.bf16.f32 " \
                 "{%0,%1,%2,%3},{%4,%5,%6,%7},{%8,%9},{%0,%1,%2,%3};" \
                 : "+f"((c)[0]), "+f"((c)[1]), "+f"((c)[2]), "+f"((c)[3]) \
                 : "r"(a0), "r"(a1), "r"(a2), "r"(a3), "r"(b0), "r"(b1))
#define CPA16(dst, src) \
    asm volatile("cp.async.cg.shared.global [%0], [%1], 16;" :: "r"(dst), "l"(src))
#define CPA_COMMIT() asm volatile("cp.async.commit_group;" ::: "memory")

// ======================= smem layout =======================
// A_h[64][264 bf16] stride 528B; B ring: 3 bufs of 128 codes x (64 bf16 + pad) stride 144B
#define SA_H   0
#define SB_B   33792
#define SB_STR 144
#define SB_SZ  18432
#define S_EN   89088
#define S_RMIN 89600
#define S_CNT  89856
#define S_LIST 90112
#define S_OVFN 96256
#define S_OVFR 96260
#define SMEM_TOTAL 96576

// ======================= small kernels =======================
__global__ void k_init() {
    int t = blockIdx.x * blockDim.x + threadIdx.x;
    if (t < KK) { g_counts[t] = 0; g_cursor[t] = 0; }
    if (t == 0) { g_mse = 0.f; g_ortho = 0.f; }
}

__global__ __launch_bounds__(256) void k_embh(const float* __restrict__ emb) {
    int i = blockIdx.x * 256 + threadIdx.x;  // over KK*DD/4
    float4 v = ((const float4*)emb)[i];
    unsigned short h0 = __bfloat16_as_ushort(__float2bfloat16(v.x));
    unsigned short h1 = __bfloat16_as_ushort(__float2bfloat16(v.y));
    unsigned short h2 = __bfloat16_as_ushort(__float2bfloat16(v.z));
    unsigned short h3 = __bfloat16_as_ushort(__float2bfloat16(v.w));
    uint2 u;
    u.x = (uint32_t)h0 | ((uint32_t)h1 << 16);
    u.y = (uint32_t)h2 | ((uint32_t)h3 << 16);
    ((uint2*)g_eh)[i] = u;
}

__global__ __launch_bounds__(256) void k_norms(const float* __restrict__ flat,
                                               const float* __restrict__ emb) {
    int warp = (blockIdx.x * blockDim.x + threadIdx.x) >> 5;
    int lane = threadIdx.x & 31;
    if (warp >= NN + KK) return;
    const float4* p4 = (warp < NN)
        ? (const float4*)(flat + (size_t)warp * DD)
        : (const float4*)(emb + (size_t)(warp - NN) * DD);
    float s = 0.f;
#pragma unroll
    for (int c = 0; c < 2; c++) {
        float4 v = p4[lane + 32 * c];
        s += v.x * v.x + v.y * v.y + v.z * v.z + v.w * v.w;
    }
#pragma unroll
    for (int o = 16; o; o >>= 1) s += __shfl_xor_sync(0xffffffffu, s, o);
    if (lane == 0) {
        if (warp < NN) g_xnorm[warp] = s;
        else           g_enorm[warp - NN] = s;
    }
}

// exact fp32 rescore of one (row, code) distance — reference-style rounding
__device__ __forceinline__ float exact_dist(const float4* __restrict__ f4,
                                            const float4* __restrict__ e4,
                                            int n, int k, float xn) {
    float s0 = 0.f, s1 = 0.f, s2 = 0.f, s3 = 0.f;
#pragma unroll 8
    for (int c = 0; c < 64; c++) {
        float4 x = f4[(size_t)n * 64 + c];
        float4 e = e4[(size_t)k * 64 + c];
        s0 += x.x * e.x; s1 += x.y * e.y; s2 += x.z * e.z; s3 += x.w * e.w;
    }
    float dot = (s0 + s1) + (s2 + s3);
    return (xn + g_enorm[k]) - 2.0f * dot;
}

// ======================= bf16 HMMA argmin (hh-only + candidate superset) =======================
// CTA: 256 threads = 8 warps (wm 0..1 x 32 rows, wn 0..3 x 32 cols); 64 rows x 1024 codes.
// 2 CTAs/SM co-resident: independent barriers/cp.async waits overlap across CTAs.
// A holds bf16(-2x); approx d = (1+||e||^2) + acc. Collect codes < running_min + GAP_EPS
// (12-sigma superset), exact fp32 rescore; full-scan fallback on CAP overflow.
__global__ __launch_bounds__(256, 2) void k_argmin_mma(const float* __restrict__ flat,
                                                       const float* __restrict__ emb,
                                                       float* __restrict__ out_idx) {
    extern __shared__ __align__(16) char smem[];
    uint32_t sb = smem_to_u32(smem);
    int tid = threadIdx.x;
    int lane = tid & 31, wid = tid >> 5;
    int wm = wid >> 2, wn = wid & 3;
    int rowbase = blockIdx.x * 64;

    float* s_en   = (float*)(smem + S_EN);
    int*   s_rmin = (int*)(smem + S_RMIN);
    int*   s_cnt  = (int*)(smem + S_CNT);
    int*   s_list = (int*)(smem + S_LIST);
    int*   s_novf = (int*)(smem + S_OVFN);
    int*   s_ovfr = (int*)(smem + S_OVFR);

    // ---- phase 0: load A fp32, store bf16(-2x) into persistent smem ----
    const float4* f4 = (const float4*)flat;
#pragma unroll
    for (int it = 0; it < 16; it++) {
        int idx = it * 256 + tid;
        int r = idx >> 6, c4 = idx & 63;
        float4 v = f4[((size_t)(rowbase + r)) * 64 + c4];
        unsigned short h0 = __bfloat16_as_ushort(__float2bfloat16(-2.0f * v.x));
        unsigned short h1 = __bfloat16_as_ushort(__float2bfloat16(-2.0f * v.y));
        unsigned short h2 = __bfloat16_as_ushort(__float2bfloat16(-2.0f * v.z));
        unsigned short h3 = __bfloat16_as_ushort(__float2bfloat16(-2.0f * v.w));
        uint2 u;
        u.x = (uint32_t)h0 | ((uint32_t)h1 << 16);
        u.y = (uint32_t)h2 | ((uint32_t)h3 << 16);
        *(uint2*)(smem + SA_H + r * 528 + c4 * 8) = u;
    }
    if (tid < 64) {
        s_rmin[tid] = 0x7f7fffff;       // +FLT_MAX bits (positive-float int order)
        s_cnt[tid] = 0;
    }
    if (tid < 128) s_en[tid] = 1.0f + g_enorm[tid];  // bias keeps scores positive
    if (tid == 0) *s_novf = 0;

    float acc[2][4][4];
#pragma unroll
    for (int i = 0; i < 2; i++)
#pragma unroll
        for (int nf = 0; nf < 4; nf++)
#pragma unroll
            for (int c = 0; c < 4; c++) acc[i][nf][c] = 0.f;

    // lane-derived ldmatrix addressing
    int a_row = lane & 15;
    int a_kof = (lane >> 4) * 8;
    int b_nof = (lane & 7) + ((lane >> 4) & 1) * 8;
    int b_kof = ((lane >> 3) & 1) * 8;
    int pr = tid >> 1, pq = tid & 1;  // prefetch row / 64B half

    // prefetch global chunk 0 (chunk gc: nt=gc>>2 codes, ci=gc&3 64-dim slice)
    {
        const char* gs = (const char*)g_eh + (size_t)pr * 512 + pq * 64;
        uint32_t ds = sb + SB_B + pr * SB_STR + pq * 64;
        CPA16(ds, gs); CPA16(ds + 16, gs + 16); CPA16(ds + 32, gs + 32); CPA16(ds + 48, gs + 48);
        CPA_COMMIT();
    }

    for (int gc = 0; gc < 32; gc++) {
        int nt = gc >> 2, ci = gc & 3;
        if (gc < 31) {
            int nt2 = (gc + 1) >> 2, ci2 = (gc + 1) & 3;
            const char* gs = (const char*)g_eh + ((size_t)(nt2 * 128 + pr)) * 512 + ci2 * 128 + pq * 64;
            uint32_t ds = sb + SB_B + ((gc + 1) % 3) * SB_SZ + pr * SB_STR + pq * 64;
            CPA16(ds, gs); CPA16(ds + 16, gs + 16); CPA16(ds + 32, gs + 32); CPA16(ds + 48, gs + 48);
            CPA_COMMIT();
            asm volatile("cp.async.wait_group 1;" ::: "memory");
        } else {
            asm volatile("cp.async.wait_group 0;" ::: "memory");
        }
        __syncthreads();  // chunk gc visible; 3-buf ring covers WAR

        int kb = ci * 64;
        uint32_t bbase = sb + SB_B + (gc % 3) * SB_SZ;
#pragma unroll
        for (int kk = 0; kk < 4; kk++) {
            uint32_t b[2][4];
#pragma unroll
            for (int p = 0; p < 2; p++) {
                uint32_t bd = bbase + (uint32_t)(wn * 32 + p * 16 + b_nof) * SB_STR
                            + (uint32_t)(kk * 16 + b_kof) * 2u;
                LDSM_X4(b[p][0], b[p][1], b[p][2], b[p][3], bd);
            }
            uint32_t a[2][4];
#pragma unroll
            for (int i = 0; i < 2; i++) {
                uint32_t ad = sb + SA_H + (uint32_t)(wm * 32 + i * 16 + a_row) * 528u
                            + (uint32_t)(kb + kk * 16 + a_kof) * 2u;
                LDSM_X4(a[i][0], a[i][1], a[i][2], a[i][3], ad);
            }
#pragma unroll
            for (int i = 0; i < 2; i++) {
                MMA16816(acc[i][0], a[i][0], a[i][1], a[i][2], a[i][3], b[0][0], b[0][1]);
                MMA16816(acc[i][1], a[i][0], a[i][1], a[i][2], a[i][3], b[0][2], b[0][3]);
                MMA16816(acc[i][2], a[i][0], a[i][1], a[i][2], a[i][3], b[1][0], b[1][1]);
                MMA16816(acc[i][3], a[i][0], a[i][1], a[i][2], a[i][3], b[1][2], b[1][3]);
            }
        }

        if (ci == 3) {
            // ---- transform acc -> d, track per-row-slot local min ----
            float m[4] = {3.4e38f, 3.4e38f, 3.4e38f, 3.4e38f};
#pragma unroll
            for (int nf = 0; nf < 4; nf++) {
                int cb = wn * 32 + nf * 8 + (lane & 3) * 2;
                float e0 = s_en[cb], e1 = s_en[cb + 1];
#pragma unroll
                for (int i = 0; i < 2; i++) {
                    float d0 = acc[i][nf][0] + e0; acc[i][nf][0] = d0;
                    float d1 = acc[i][nf][1] + e1; acc[i][nf][1] = d1;
                    float d2 = acc[i][nf][2] + e0; acc[i][nf][2] = d2;
                    float d3 = acc[i][nf][3] + e1; acc[i][nf][3] = d3;
                    m[i * 2]     = fminf(m[i * 2],     fminf(d0, d1));
                    m[i * 2 + 1] = fminf(m[i * 2 + 1], fminf(d2, d3));
                }
            }
#pragma unroll
            for (int s = 0; s < 4; s++) {
                int row = wm * 32 + (s >> 1) * 16 + (s & 1) * 8 + (lane >> 2);
                atomicMin(&s_rmin[row], __float_as_int(m[s]));
            }
            __syncthreads();
            float thr[4];
#pragma unroll
            for (int s = 0; s < 4; s++) {
                int row = wm * 32 + (s >> 1) * 16 + (s & 1) * 8 + (lane >> 2);
                thr[s] = __int_as_float(s_rmin[row]) + GAP_EPS;
            }
#pragma unroll
            for (int i = 0; i < 2; i++)
#pragma unroll
                for (int nf = 0; nf < 4; nf++)
#pragma unroll
                    for (int c = 0; c < 4; c++) {
                        int s = i * 2 + (c >> 1);
                        if (acc[i][nf][c] < thr[s]) {
                            int row = wm * 32 + i * 16 + (c >> 1) * 8 + (lane >> 2);
                            int k = nt * 128 + wn * 32 + nf * 8 + (lane & 3) * 2 + (c & 1);
                            int pos = atomicAdd(&s_cnt[row], 1);
                            if (pos < CAP) s_list[row * CAP + pos] = k;
                        }
                        acc[i][nf][c] = 0.f;
                    }
            if (tid < 128 && nt < 7) s_en[tid] = 1.0f + g_enorm[(nt + 1) * 128 + tid];
        }
    }
    __syncthreads();  // all collections done

    // ---- exact rescore of candidate superset (reference semantics) ----
    const float4* e4 = (const float4*)emb;
    if (tid < 64) {
        int c = s_cnt[tid];
        int n = rowbase + tid;
        if (c > CAP) {
            int p = atomicAdd(s_novf, 1);
            s_ovfr[p] = tid;
        } else {
            float xn = g_xnorm[n];
            float bv = 3.4e38f;
            int bk = 1 << 30;
            for (int j = 0; j < c; j++) {
                int k = s_list[tid * CAP + j];
                float d = exact_dist(f4, e4, n, k, xn);
                if (d < bv || (d == bv && k < bk)) { bv = d; bk = k; }
            }
            g_idx[n] = bk;
            atomicAdd(&g_counts[bk], 1);
            if (out_idx) out_idx[n] = (float)bk;
        }
    }
    __syncthreads();
    // overflow fallback: warp-cooperative exact full scan (statistically ~never taken)
    int nov = *s_novf;
    for (int o = wid; o < nov; o += 8) {
        int rl = s_ovfr[o];
        int n = rowbase + rl;
        float xn = g_xnorm[n];
        float bv = 3.4e38f;
        int bk = 1 << 30;
        for (int k = lane; k < KK; k += 32) {
            float d = exact_dist(f4, e4, n, k, xn);
            if (d < bv || (d == bv && k < bk)) { bv = d; bk = k; }
        }
#pragma unroll
        for (int off = 16; off; off >>= 1) {
            float ov = __shfl_xor_sync(0xffffffffu, bv, off);
            int ok = __shfl_xor_sync(0xffffffffu, bk, off);
            if (ov < bv || (ov == bv && ok < bk)) { bv = ov; bk = ok; }
        }
        if (lane == 0) {
            g_idx[n] = bk;
            atomicAdd(&g_counts[bk], 1);
            if (out_idx) out_idx[n] = (float)bk;
        }
    }
}

// ======================= EMA / losses (as R10) =======================
__global__ void k_scan(const float* __restrict__ ema_cs, float* __restrict__ out_ncs) {
    __shared__ int   sc[KK];
    __shared__ float red[KK];
    int t = threadIdx.x;
    int c = g_counts[t];
    float ncs = DECAYV * ema_cs[t] + (1.0f - DECAYV) * (float)c;
    g_ncs[t] = ncs;
    if (out_ncs) out_ncs[t] = ncs;
    red[t] = ncs;
    __syncthreads();
#pragma unroll
    for (int o = 512; o; o >>= 1) {
        if (t < o) red[t] += red[t + o];
        __syncthreads();
    }
    if (t == 0) g_ntotal = red[0] + EPSV;
    sc[t] = c;
    __syncthreads();
    for (int o = 1; o < KK; o <<= 1) {
        int u = (t >= o) ? sc[t - o] : 0;
        __syncthreads();
        sc[t] += u;
        __syncthreads();
    }
    g_offsets[t] = sc[t] - c;
}

__global__ __launch_bounds__(256) void k_scatter() {
    int n = blockIdx.x * 256 + threadIdx.x;
    int k = g_idx[n];
    int pos = atomicAdd(&g_cursor[k], 1);
    g_bucket[g_offsets[k] + pos] = n;
}

__global__ __launch_bounds__(256) void k_codesum(const float* __restrict__ flat,
                                                 const float* __restrict__ ema_avg,
                                                 float* __restrict__ out_ne,
                                                 float* __restrict__ out_nea) {
    __shared__ int sn[256];
    int k = blockIdx.x;
    int d = threadIdx.x;
    int start = g_offsets[k];
    int cnt = g_counts[k];
    float s = 0.f;
    for (int base = 0; base < cnt; base += 256) {
        int m = min(256, cnt - base);
        __syncthreads();
        if (d < m) sn[d] = g_bucket[start + base + d];
        __syncthreads();
        int t = 0;
        for (; t + 4 <= m; t += 4) {
            float v0 = flat[(size_t)sn[t + 0] * DD + d];
            float v1 = flat[(size_t)sn[t + 1] * DD + d];
            float v2 = flat[(size_t)sn[t + 2] * DD + d];
            float v3 = flat[(size_t)sn[t + 3] * DD + d];
            s += ((v0 + v1) + (v2 + v3));
        }
        for (; t < m; t++) s += flat[(size_t)sn[t] * DD + d];
    }
    float navg = DECAYV * ema_avg[(size_t)k * DD + d] + (1.0f - DECAYV) * s;
    if (out_nea) out_nea[(size_t)k * DD + d] = navg;
    float cs = (g_ncs[k] + EPSV) / g_ntotal;
    if (out_ne) out_ne[(size_t)k * DD + d] = navg / cs;
}

__global__ __launch_bounds__(256) void k_quant(const float* __restrict__ flat,
                                               const float* __restrict__ emb,
                                               float* __restrict__ out_q) {
    int tid = threadIdx.x;
    int c = tid & 63;
    int rs = tid >> 6;
    int base = blockIdx.x * 64;
    const float4* f4 = (const float4*)flat;
    const float4* e4 = (const float4*)emb;
    float4* o4 = (float4*)out_q;
    float acc = 0.f;
#pragma unroll 4
    for (int it = 0; it < 16; it++) {
        int n = base + it * 4 + rs;
        int k = g_idx[n];
        float4 x = f4[(size_t)n * 64 + c];
        float4 e = e4[(size_t)k * 64 + c];
        float dx = e.x - x.x, dy = e.y - x.y, dz = e.z - x.z, dw = e.w - x.w;
        acc += dx * dx + dy * dy + dz * dz + dw * dw;
        if (out_q) {
            float4 st;
            st.x = x.x + dx; st.y = x.y + dy; st.z = x.z + dz; st.w = x.w + dw;
            o4[(size_t)n * 64 + c] = st;
        }
    }
    __shared__ float red[256];
    red[tid] = acc;
    __syncthreads();
#pragma unroll
    for (int o = 128; o; o >>= 1) {
        if (tid < o) red[tid] += red[tid + o];
        __syncthreads();
    }
    if (tid == 0) atomicAdd(&g_mse, red[0]);
}

__global__ __launch_bounds__(256) void k_ortho(const float* __restrict__ emb) {
    __shared__ float Ei[32][65];
    __shared__ float Ej[32][65];
    int bi = blockIdx.x >> 5;
    int bj = blockIdx.x & 31;
    int tid = threadIdx.x;
    int tx = tid & 15, ty = tid >> 4;
    const float4* e4 = (const float4*)emb;
    float acc[2][2] = {{0.f, 0.f}, {0.f, 0.f}};
    for (int dc = 0; dc < 4; dc++) {
#pragma unroll
        for (int s = 0; s < 2; s++) {
            int i = s * 256 + tid;
            int r = i >> 4, c = i & 15;
            float4 va = e4[(size_t)(bi * 32 + r) * 64 + dc * 16 + c];
            Ei[r][c * 4 + 0] = va.x; Ei[r][c * 4 + 1] = va.y;
            Ei[r][c * 4 + 2] = va.z; Ei[r][c * 4 + 3] = va.w;
            float4 vb = e4[(size_t)(bj * 32 + r) * 64 + dc * 16 + c];
            Ej[r][c * 4 + 0] = vb.x; Ej[r][c * 4 + 1] = vb.y;
            Ej[r][c * 4 + 2] = vb.z; Ej[r][c * 4 + 3] = vb.w;
        }
        __syncthreads();
#pragma unroll 8
        for (int d = 0; d < 64; d++) {
            float a0 = Ei[ty * 2 + 0][d], a1 = Ei[ty * 2 + 1][d];
            float b0 = Ej[tx * 2 + 0][d], b1 = Ej[tx * 2 + 1][d];
            acc[0][0] += a0 * b0; acc[0][1] += a0 * b1;
            acc[1][0] += a1 * b0; acc[1][1] += a1 * b1;
        }
        __syncthreads();
    }
    float s = 0.f;
#pragma unroll
    for (int ii = 0; ii < 2; ii++)
#pragma unroll
        for (int jj = 0; jj < 2; jj++) {
            int gi = bi * 32 + ty * 2 + ii;
            int gj = bj * 32 + tx * 2 + jj;
            if (gi != gj) s += acc[ii][jj] * acc[ii][jj];
        }
    __shared__ float red[256];
    red[tid] = s;
    __syncthreads();
#pragma unroll
    for (int o = 128; o; o >>= 1) {
        if (tid < o) red[tid] += red[tid + o];
        __syncthreads();
    }
    if (tid == 0) atomicAdd(&g_ortho, red[0]);
}

__global__ void k_loss(float* __restrict__ out_loss) {
    float mse_mean = g_mse / 33554432.0f;
    float loss = mse_mean + 0.25f * mse_mean + 0.09f * sqrtf(g_ortho);
    if (out_loss) *out_loss = loss;
}

// ---------------------------------------------------------------------------
extern "C" void kernel_launch(void* const* d_in, const int* in_sizes, int n_in,
                              void* d_out, int out_size) {
    const float* flat    = (const float*)d_in[0];
    const float* emb     = (const float*)d_in[1];
    const float* ema_cs  = (const float*)d_in[2];
    const float* ema_avg = (const float*)d_in[3];
    float* out = (float*)d_out;

    const int FULL = 34210817;
    bool isfull = (out_size >= FULL);
    float* out_q    = out;
    float* out_loss = isfull ? out + 33554432 : nullptr;
    float* out_idx  = isfull ? out + 33554433 : nullptr;
    float* out_ne   = isfull ? out + 33685505 : nullptr;
    float* out_ncs  = isfull ? out + 33947649 : nullptr;
    float* out_nea  = isfull ? out + 33948673 : nullptr;

    cudaFuncSetAttribute(k_argmin_mma, cudaFuncAttributeMaxDynamicSharedMemorySize, SMEM_TOTAL);

    k_init<<<4, 256>>>();
    k_embh<<<KK * DD / 4 / 256, 256>>>(emb);
    k_norms<<<(NN + KK) / 8, 256>>>(flat, emb);
    k_argmin_mma<<<NN / 64, 256, SMEM_TOTAL>>>(flat, emb, out_idx);
    k_scan<<<1, 1024>>>(ema_cs, out_ncs);
    k_scatter<<<NN / 256, 256>>>();
    k_codesum<<<KK, 256>>>(flat, ema_avg, out_ne, out_nea);
    k_quant<<<NN / 64, 256>>>(flat, emb, out_q);
    k_ortho<<<1024, 256>>>(emb);
    k_loss<<<1, 1>>>(out_loss);
}